// round 9
// baseline (speedup 1.0000x reference)
#include <cuda_runtime.h>

#define N_NODES 50000
#define N_EDGES 800000
#define D 128
#define NBATCH 64

// ---------------- device scratch (allocation-free) ----------------
__device__ int   g_deg[N_NODES];          // per-dst degree (zeroed each call)
__device__ int   g_rowstart[N_NODES + 1]; // CSR row offsets
__device__ int   g_cursor[N_NODES];       // fill cursors
__device__ int   g_csr[N_EDGES];          // src indices grouped by dst
__device__ float g_S[NBATCH * D];         // per-batch pooled sums (zeroed each call)

// ---------------------------------------------------------------------------
// 0) zero degree + pooled accumulators
// ---------------------------------------------------------------------------
__global__ void k_setup() {
    int i = blockIdx.x * blockDim.x + threadIdx.x;
    if (i < N_NODES)    g_deg[i] = 0;
    if (i < NBATCH * D) g_S[i] = 0.0f;
}

// ---------------------------------------------------------------------------
// 1) histogram of dst
// ---------------------------------------------------------------------------
__global__ void k_hist(const int* __restrict__ ei) {
    int e = blockIdx.x * blockDim.x + threadIdx.x;
    if (e < N_EDGES) atomicAdd(&g_deg[__ldg(&ei[N_EDGES + e])], 1);
}

// ---------------------------------------------------------------------------
// 2) exclusive scan of g_deg -> g_rowstart (+ cursor copy). One 1024-thr block.
// ---------------------------------------------------------------------------
__global__ void k_scan() {
    __shared__ int sums[1024];
    const int CHUNK = (N_NODES + 1023) / 1024;   // 49
    int t = threadIdx.x;
    int beg = t * CHUNK;
    int end = beg + CHUNK; if (end > N_NODES) end = N_NODES;

    int s = 0;
    for (int i = beg; i < end; i++) s += g_deg[i];
    sums[t] = s;
    __syncthreads();
    for (int off = 1; off < 1024; off <<= 1) {
        int v = (t >= off) ? sums[t - off] : 0;
        __syncthreads();
        sums[t] += v;
        __syncthreads();
    }
    int run = (t == 0) ? 0 : sums[t - 1];
    for (int i = beg; i < end; i++) {
        g_rowstart[i] = run;
        g_cursor[i]   = run;
        run += g_deg[i];
    }
    if (t == 0) g_rowstart[N_NODES] = N_EDGES;
}

// ---------------------------------------------------------------------------
// 3) permute: csr[cursor[dst]++] = src
// ---------------------------------------------------------------------------
__global__ void k_fill(const int* __restrict__ ei) {
    int e = blockIdx.x * blockDim.x + threadIdx.x;
    if (e >= N_EDGES) return;
    int src = __ldg(&ei[e]);
    int dst = __ldg(&ei[N_EDGES + e]);
    int p = atomicAdd(&g_cursor[dst], 1);
    g_csr[p] = src;
}

// ---------------------------------------------------------------------------
// 4) fused gather-aggregate: one warp per dst row, lane = one float4.
//    out[r] = relu(scale*x[r] + sum_{s in N(r)} x[s]);
//    pooled partial: one red.global.add.v4 per row into g_S[batch[r]].
//    Gather-only: 512B/edge read + 512B/node write — no RMW traffic.
// ---------------------------------------------------------------------------
__global__ void __launch_bounds__(256) k_agg(const float* __restrict__ x,
                                             const float* __restrict__ eps,
                                             const int* __restrict__ batch,
                                             float* __restrict__ out) {
    int row  = (blockIdx.x * blockDim.x + threadIdx.x) >> 5;
    int lane = threadIdx.x & 31;
    if (row >= N_NODES) return;

    const float4* x4 = reinterpret_cast<const float4*>(x);
    float scale = 1.0f + eps[0];

    float4 xr = x4[(size_t)row * 32 + lane];
    float4 acc;
    acc.x = xr.x * scale; acc.y = xr.y * scale;
    acc.z = xr.z * scale; acc.w = xr.w * scale;

    int s0 = g_rowstart[row];
    int s1 = g_rowstart[row + 1];
    for (int base = s0; base < s1; base += 32) {
        int n = s1 - base; if (n > 32) n = 32;
        int idx = (base + lane < s1) ? g_csr[base + lane] : 0;   // coalesced
        #pragma unroll 4
        for (int j = 0; j < n; j++) {
            int s = __shfl_sync(0xffffffffu, idx, j);
            float4 v = __ldcg(&x4[(size_t)s * 32 + lane]);
            acc.x += v.x; acc.y += v.y; acc.z += v.z; acc.w += v.w;
        }
    }

    acc.x = fmaxf(acc.x, 0.0f); acc.y = fmaxf(acc.y, 0.0f);
    acc.z = fmaxf(acc.z, 0.0f); acc.w = fmaxf(acc.w, 0.0f);
    reinterpret_cast<float4*>(out)[(size_t)row * 32 + lane] = acc;

    // pooled partial sum straight into g_S (3.2 MB of REDs total: cheap)
    int b = __ldg(&batch[row]);     // broadcast
    float* p = &g_S[b * D + lane * 4];
    asm volatile("red.global.add.v4.f32 [%0], {%1, %2, %3, %4};"
                 :: "l"(p), "f"(acc.x), "f"(acc.y), "f"(acc.z), "f"(acc.w)
                 : "memory");
}

// ---------------------------------------------------------------------------
// 5) pooled2[b] = S[b] @ W + cnt[b]*bias. cnt via binary search in sorted
//    batch (no atomics). 4 independent FMA chains, full unroll.
// ---------------------------------------------------------------------------
__device__ __forceinline__ int lower_bound_batch(const int* batch, int val) {
    int lo = 0, hi = N_NODES;
    while (lo < hi) {
        int mid = (lo + hi) >> 1;
        if (batch[mid] < val) lo = mid + 1; else hi = mid;
    }
    return lo;
}

__global__ void k_pool(const float* __restrict__ W,
                       const float* __restrict__ bias,
                       const int* __restrict__ batch,
                       float* __restrict__ out2) {
    int b = blockIdx.x;     // 0..63
    int j = threadIdx.x;    // 0..127
    __shared__ float s[D];
    __shared__ float cntf;
    s[j] = g_S[b * D + j];
    if (j == 0)
        cntf = (float)(lower_bound_batch(batch, b + 1) - lower_bound_batch(batch, b));
    __syncthreads();

    float a0 = 0.f, a1 = 0.f, a2 = 0.f, a3 = 0.f;
    #pragma unroll
    for (int k = 0; k < D; k += 4) {
        a0 = fmaf(s[k + 0], __ldg(&W[(k + 0) * D + j]), a0);
        a1 = fmaf(s[k + 1], __ldg(&W[(k + 1) * D + j]), a1);
        a2 = fmaf(s[k + 2], __ldg(&W[(k + 2) * D + j]), a2);
        a3 = fmaf(s[k + 3], __ldg(&W[(k + 3) * D + j]), a3);
    }
    out2[b * D + j] = cntf * bias[j] + ((a0 + a1) + (a2 + a3));
}

// ---------------------------------------------------------------------------
// launch: x, eps, W_pred, b_pred, edge_index, batch -> out | pooled2
// ---------------------------------------------------------------------------
extern "C" void kernel_launch(void* const* d_in, const int* in_sizes, int n_in,
                              void* d_out, int out_size) {
    const float* x     = (const float*)d_in[0];
    const float* eps   = (const float*)d_in[1];
    const float* Wp    = (const float*)d_in[2];
    const float* bp    = (const float*)d_in[3];
    const int*   ei    = (const int*)d_in[4];
    const int*   batch = (const int*)d_in[5];

    float* out  = (float*)d_out;
    float* out2 = out + (size_t)N_NODES * D;

    k_setup<<<(N_NODES + 255) / 256, 256>>>();
    k_hist <<<(N_EDGES + 255) / 256, 256>>>(ei);
    k_scan <<<1, 1024>>>();
    k_fill <<<(N_EDGES + 255) / 256, 256>>>(ei);

    {
        long long threads = (long long)N_NODES * 32;
        int blocks = (int)((threads + 255) / 256);           // 6250
        k_agg<<<blocks, 256>>>(x, eps, batch, out);
    }

    k_pool<<<NBATCH, 128>>>(Wp, bp, batch, out2);
}